// round 15
// baseline (speedup 1.0000x reference)
#include <cuda_runtime.h>
#include <cuda_bf16.h>
#include <math.h>
#include <stdint.h>

#define Bdim 4096
#define Ldim 32
#define LOG2E 1.4426950408889634f

// ---------------- scratch (device globals; no allocation allowed) ----------
__device__ float         g_h[2][(size_t)Bdim * 512];       // fp32 hidden
__device__ __nv_bfloat16 g_abf[2][(size_t)Bdim * 768];     // [e | h] bf16
__device__ __nv_bfloat16 g_grzb[(size_t)Bdim * 1024];      // sigma(r)|sigma(z) bf16
__device__ __nv_bfloat16 g_inb[(size_t)Bdim * 512];        // i_n (+b) bf16
__device__ float         g_logits[(size_t)Bdim * 512];
__device__ __nv_bfloat16 g_xbf[(size_t)Bdim * 512];
__device__ __nv_bfloat16 g_wrz[1024 * 768];
__device__ __nv_bfloat16 g_wihn[512 * 256];
__device__ __nv_bfloat16 g_whhn[512 * 512];
__device__ __nv_bfloat16 g_wo[512 * 512];
__device__ __nv_bfloat16 g_we[256 * 512];
__device__ __nv_bfloat16 g_wa[512 * 512];
__device__ float         g_brz[1024];

__device__ __forceinline__ float sigm(float x) { return 1.f / (1.f + expf(-x)); }

#define MMA_BF16(d, a, b) \
    asm volatile("mma.sync.aligned.m16n8k16.row.col.f32.bf16.bf16.f32 " \
        "{%0,%1,%2,%3}, {%4,%5,%6,%7}, {%8,%9}, {%0,%1,%2,%3};" \
        : "+f"((d)[0]), "+f"((d)[1]), "+f"((d)[2]), "+f"((d)[3]) \
        : "r"((a)[0]), "r"((a)[1]), "r"((a)[2]), "r"((a)[3]), \
          "r"((b)[0]), "r"((b)[1]))

#define LDM_X4(d, addr) \
    asm volatile("ldmatrix.sync.aligned.m8n8.x4.shared.b16 {%0,%1,%2,%3}, [%4];" \
        : "=r"((d)[0]), "=r"((d)[1]), "=r"((d)[2]), "=r"((d)[3]) : "r"(addr))

__device__ __forceinline__ void cp16(uint32_t dst, const void* src) {
    asm volatile("cp.async.cg.shared.global [%0], [%1], 16;" :: "r"(dst), "l"(src) : "memory");
}
#define CP_COMMIT  asm volatile("cp.async.commit_group;" ::: "memory")
#define CP_WAIT2   asm volatile("cp.async.wait_group 2;" ::: "memory")

#define SWZ(r, c) ((uint32_t)((((r) << 2) + ((c) ^ (((r) >> 1) & 3))) << 4))

// ---------------- single segmented prep kernel ------------------------------
__global__ void prep_all(
    const float* __restrict__ x, const float* __restrict__ Wih,
    const float* __restrict__ Whh, const float* __restrict__ bih,
    const float* __restrict__ bhh, const float* __restrict__ Wo,
    const float* __restrict__ We, const float* __restrict__ Wa,
    const float* __restrict__ sos)
{
    size_t i = (size_t)blockIdx.x * 256 + threadIdx.x;
    if (i < 786432) {                       // wrz [1024 x 768]
        int g = (int)(i / 768), c = (int)(i % 768);
        float v = (c < 256) ? Wih[g * 256 + c] : Whh[g * 512 + (c - 256)];
        g_wrz[i] = __float2bfloat16_rn(v);
    } else if (i < 917504) {                // wihn
        size_t t = i - 786432;
        g_wihn[t] = __float2bfloat16_rn(Wih[1024 * 256 + t]);
    } else if (i < 1179648) {               // whhn
        size_t t = i - 917504;
        g_whhn[t] = __float2bfloat16_rn(Whh[1024 * 512 + t]);
    } else if (i < 1441792) {               // wo
        size_t t = i - 1179648;
        g_wo[t] = __float2bfloat16_rn(Wo[t]);
    } else if (i < 1572864) {               // we
        size_t t = i - 1441792;
        g_we[t] = __float2bfloat16_rn(We[t]);
    } else if (i < 1835008) {               // wa
        size_t t = i - 1572864;
        g_wa[t] = __float2bfloat16_rn(Wa[t]);
    } else if (i < 3932160) {               // xbf
        size_t t = i - 1835008;
        g_xbf[t] = __float2bfloat16_rn(x[t]);
    } else if (i < 4980736) {               // e0 broadcast
        size_t t = i - 3932160;
        int b = (int)(t >> 8), c = (int)(t & 255);
        g_abf[0][(size_t)b * 768 + c] = __float2bfloat16_rn(sos[c]);
    } else if (i < 4981760) {               // brz
        size_t t = i - 4980736;
        g_brz[t] = bih[t] + bhh[t];
    }
}

// =================== GEMM mainloop (device function) ========================
template<int MFR>
__device__ __forceinline__ void gemm_mainloop(
    char* smem, int tid,
    const __nv_bfloat16* __restrict__ A, int lda,
    const __nv_bfloat16* __restrict__ W, int ldw, int KB,
    int m0, int n0, float acc[MFR][8][4])
{
    constexpr int AS = MFR * 2048;
    constexpr int SS = AS + 8192;
    const int wid = tid >> 5, lane = tid & 31;
    const int wm = wid & 1, wn = wid >> 1;
    const uint32_t smbase = (uint32_t)__cvta_generic_to_shared(smem);

#pragma unroll
    for (int a_ = 0; a_ < MFR; a_++)
#pragma unroll
        for (int b_ = 0; b_ < 8; b_++)
#pragma unroll
            for (int c_ = 0; c_ < 4; c_++) acc[a_][b_][c_] = 0.f;

    const int cr = tid >> 2, cc = tid & 3;
    auto issue = [&](int kb, int s) {
        uint32_t sb = smbase + (uint32_t)s * SS;
#pragma unroll
        for (int it = 0; it < MFR; ++it) {
            int rr = cr + (it << 5);
            cp16(sb + SWZ(rr, cc), A + (size_t)(m0 + rr) * lda + (kb << 5) + (cc << 3));
        }
#pragma unroll
        for (int it = 0; it < 4; ++it) {
            int rr = cr + (it << 5);
            cp16(sb + AS + SWZ(rr, cc), W + (size_t)(n0 + rr) * ldw + (kb << 5) + (cc << 3));
        }
    };
    const int arow0 = wm * (MFR << 4) + (lane & 7) + (((lane >> 3) & 1) << 3);
    const int acb   = (lane >> 4) & 1;
    const int nrow0 = (wn << 6) + (lane & 7) + (((lane >> 4) & 1) << 3);
    const int bcb   = (lane >> 3) & 1;

    issue(0, 0); CP_COMMIT;
    issue(1, 1); CP_COMMIT;
    issue(2, 2); CP_COMMIT;
#pragma unroll 1
    for (int kb = 0; kb < KB; ++kb) {
        CP_WAIT2;
        __syncthreads();
        if (kb + 3 < KB) issue(kb + 3, (kb + 3) & 3);
        CP_COMMIT;
        uint32_t ab = smbase + (uint32_t)(kb & 3) * SS, bb = ab + AS;
#pragma unroll
        for (int ks = 0; ks < 2; ++ks) {
            uint32_t afr[MFR][4];
#pragma unroll
            for (int mt = 0; mt < MFR; ++mt)
                LDM_X4(afr[mt], ab + SWZ(arow0 + (mt << 4), (ks << 1) + acb));
            uint32_t bfr[8][2];
#pragma unroll
            for (int p = 0; p < 4; ++p) {
                uint32_t t4[4];
                LDM_X4(t4, bb + SWZ(nrow0 + (p << 4), (ks << 1) + bcb));
                bfr[2 * p][0] = t4[0]; bfr[2 * p][1] = t4[1];
                bfr[2 * p + 1][0] = t4[2]; bfr[2 * p + 1][1] = t4[3];
            }
#pragma unroll
            for (int mt = 0; mt < MFR; ++mt)
#pragma unroll
                for (int nt = 0; nt < 8; ++nt)
                    MMA_BF16(acc[mt][nt], afr[mt], bfr[nt]);
        }
    }
}

// ---- generic fp32(+bf16) epilogue ----
template<int MFR>
__device__ __forceinline__ void epi_store(
    float acc[MFR][8][4], int tid,
    const float* __restrict__ bias,
    float* __restrict__ C, int ldc,
    __nv_bfloat16* __restrict__ Cbf, int ldcb,
    int m0, int n0)
{
    const int wid = tid >> 5, lane = tid & 31;
    const int wm = wid & 1, wn = wid >> 1;
#pragma unroll
    for (int mt = 0; mt < MFR; ++mt) {
#pragma unroll
        for (int nt = 0; nt < 8; ++nt) {
            int row = m0 + wm * (MFR << 4) + (mt << 4) + (lane >> 2);
            int col = n0 + (wn << 6) + (nt << 3) + ((lane & 3) << 1);
            float2 bv = *(const float2*)&bias[col];
            float2 o0 = {acc[mt][nt][0] + bv.x, acc[mt][nt][1] + bv.y};
            float2 o1 = {acc[mt][nt][2] + bv.x, acc[mt][nt][3] + bv.y};
            if (C) {
                *(float2*)&C[(size_t)row * ldc + col] = o0;
                *(float2*)&C[(size_t)(row + 8) * ldc + col] = o1;
            }
            if (Cbf) {
                __nv_bfloat162 p0 = {__float2bfloat16_rn(o0.x), __float2bfloat16_rn(o0.y)};
                __nv_bfloat162 p1 = {__float2bfloat16_rn(o1.x), __float2bfloat16_rn(o1.y)};
                *(__nv_bfloat162*)&Cbf[(size_t)row * ldcb + col] = p0;
                *(__nv_bfloat162*)&Cbf[(size_t)(row + 8) * ldcb + col] = p1;
            }
        }
    }
}

// ======================= generic bf16 GEMM ==================================
template<int MFR>
__global__ __launch_bounds__(128, 2) void gemm_bf(
    const __nv_bfloat16* __restrict__ A, int lda,
    const __nv_bfloat16* __restrict__ W, int K,
    const float* __restrict__ bias,
    float* __restrict__ C, int ldc,
    __nv_bfloat16* __restrict__ Cbf, int ldcb)
{
    __shared__ __align__(1024) char smem[(MFR * 2048 + 8192) * 4];
    const int tid = threadIdx.x;
    const int m0 = blockIdx.y * (MFR << 5), n0 = blockIdx.x << 7;
    float acc[MFR][8][4];
    gemm_mainloop<MFR>(smem, tid, A, lda, W, K, K >> 5, m0, n0, acc);
    epi_store<MFR>(acc, tid, bias, C, ldc, Cbf, ldcb, m0, n0);
}

// ====== merged gates kernel: rz (sigmoid->bf16) + i_n (bf16) ===============
__global__ __launch_bounds__(128, 2) void gates_kernel(
    const __nv_bfloat16* __restrict__ Ain,   // [B,768] bf16
    const __nv_bfloat16* __restrict__ wrz,   // [1024,768]
    const float* __restrict__ brz,
    const __nv_bfloat16* __restrict__ wihn,  // [512,256]
    const float* __restrict__ bihn,
    __nv_bfloat16* __restrict__ grzb,        // [B,1024] sigma bf16
    __nv_bfloat16* __restrict__ inbb)        // [B,512] bf16
{
    __shared__ __align__(1024) char smem[(4 * 2048 + 8192) * 4];
    const int tid = threadIdx.x, wid = tid >> 5, lane = tid & 31;
    const int wm = wid & 1, wn = wid >> 1;
    const int j = blockIdx.x;
    if (j < 256) {
        int m0 = (j >> 3) << 7, n0 = (j & 7) << 7;
        float acc[4][8][4];
        gemm_mainloop<4>(smem, tid, Ain, 768, wrz, 768, 24, m0, n0, acc);
        // sigmoid + bf16 epilogue
#pragma unroll
        for (int mt = 0; mt < 4; ++mt) {
#pragma unroll
            for (int nt = 0; nt < 8; ++nt) {
                int row = m0 + (wm << 6) + (mt << 4) + (lane >> 2);
                int col = n0 + (wn << 6) + (nt << 3) + ((lane & 3) << 1);
                float2 bv = *(const float2*)&brz[col];
                __nv_bfloat162 p0 = {__float2bfloat16_rn(sigm(acc[mt][nt][0] + bv.x)),
                                     __float2bfloat16_rn(sigm(acc[mt][nt][1] + bv.y))};
                __nv_bfloat162 p1 = {__float2bfloat16_rn(sigm(acc[mt][nt][2] + bv.x)),
                                     __float2bfloat16_rn(sigm(acc[mt][nt][3] + bv.y))};
                *(__nv_bfloat162*)&grzb[(size_t)row * 1024 + col] = p0;
                *(__nv_bfloat162*)&grzb[(size_t)(row + 8) * 1024 + col] = p1;
            }
        }
    } else {
        int t = j - 256;
        int m0 = (t >> 2) << 6, n0 = (t & 3) << 7;
        float acc[2][8][4];
        gemm_mainloop<2>(smem, tid, Ain, 768, wihn, 256, 8, m0, n0, acc);
        epi_store<2>(acc, tid, bihn, (float*)0, 0, inbb, 512, m0, n0);
    }
}

// ================= h_n GEMM with fused GRU update ===========================
// MFR=1: 32x128 tiles, 512 blocks, 40KB smem, 3 residents. Gates read as bf16
// (sigmoid pre-applied); fp32 master h path untouched.
__global__ __launch_bounds__(128, 3) void gemm_hn_gru(
    const __nv_bfloat16* __restrict__ A,    // h bf16 (ld 768)
    const __nv_bfloat16* __restrict__ W,    // Whh_n [512,512]
    const float* __restrict__ bias,         // b_hh_n
    const __nv_bfloat16* __restrict__ grzb, // [B,1024] sigma(r)|sigma(z) bf16
    const __nv_bfloat16* __restrict__ inbb, // [B,512] i_n (+b) bf16
    const float* __restrict__ hin,          // [B,512] fp32
    float* __restrict__ hout,
    __nv_bfloat16* __restrict__ habf)       // Anxt base; h at +256, ld 768
{
    __shared__ __align__(1024) char smem[(1 * 2048 + 8192) * 4];   // 40K
    const int tid = threadIdx.x, wid = tid >> 5, lane = tid & 31;
    const int wm = wid & 1, wn = wid >> 1;
    const int m0 = blockIdx.y << 5, n0 = blockIdx.x << 7;

    float acc[1][8][4];
    gemm_mainloop<1>(smem, tid, A, 768, W, 512, 16, m0, n0, acc);

    __syncthreads();
    float* st = (float*)smem;               // [32][132]
#pragma unroll
    for (int nt = 0; nt < 8; ++nt) {
        int rl = (wm << 4) + (lane >> 2);
        int col = (wn << 6) + (nt << 3) + ((lane & 3) << 1);
        float2 bv = *(const float2*)&bias[n0 + col];
        float2 s0 = {acc[0][nt][0] + bv.x, acc[0][nt][1] + bv.y};
        float2 s1 = {acc[0][nt][2] + bv.x, acc[0][nt][3] + bv.y};
        *(float2*)&st[rl * 132 + col] = s0;
        *(float2*)&st[(rl + 8) * 132 + col] = s1;
    }
    __syncthreads();

#pragma unroll
    for (int t = 0; t < 8; ++t) {
        int idx = tid + (t << 7);
        int r = idx >> 5, q = idx & 31;
        int rg = m0 + r, jg = n0 + (q << 2);
        float4 hn = *(float4*)&st[r * 132 + (q << 2)];
        __nv_bfloat162 rv0 = *(const __nv_bfloat162*)&grzb[(size_t)rg * 1024 + jg];
        __nv_bfloat162 rv1 = *(const __nv_bfloat162*)&grzb[(size_t)rg * 1024 + jg + 2];
        __nv_bfloat162 zv0 = *(const __nv_bfloat162*)&grzb[(size_t)rg * 1024 + 512 + jg];
        __nv_bfloat162 zv1 = *(const __nv_bfloat162*)&grzb[(size_t)rg * 1024 + 512 + jg + 2];
        __nv_bfloat162 iv0 = *(const __nv_bfloat162*)&inbb[(size_t)rg * 512 + jg];
        __nv_bfloat162 iv1 = *(const __nv_bfloat162*)&inbb[(size_t)rg * 512 + jg + 2];
        float4 hh = *(const float4*)&hin[(size_t)rg * 512 + jg];
        float4 o;
        { float rs = __bfloat162float(rv0.x), zs = __bfloat162float(zv0.x);
          o.x = (1.f - zs) * tanhf(__bfloat162float(iv0.x) + rs * hn.x) + zs * hh.x; }
        { float rs = __bfloat162float(rv0.y), zs = __bfloat162float(zv0.y);
          o.y = (1.f - zs) * tanhf(__bfloat162float(iv0.y) + rs * hn.y) + zs * hh.y; }
        { float rs = __bfloat162float(rv1.x), zs = __bfloat162float(zv1.x);
          o.z = (1.f - zs) * tanhf(__bfloat162float(iv1.x) + rs * hn.z) + zs * hh.z; }
        { float rs = __bfloat162float(rv1.y), zs = __bfloat162float(zv1.y);
          o.w = (1.f - zs) * tanhf(__bfloat162float(iv1.y) + rs * hn.w) + zs * hh.w; }
        *(float4*)&hout[(size_t)rg * 512 + jg] = o;
        __nv_bfloat162 p0 = {__float2bfloat16_rn(o.x), __float2bfloat16_rn(o.y)};
        __nv_bfloat162 p1 = {__float2bfloat16_rn(o.z), __float2bfloat16_rn(o.w)};
        __nv_bfloat162* dst = (__nv_bfloat162*)(habf + (size_t)rg * 768 + 256 + jg);
        dst[0] = p0; dst[1] = p1;
    }
}

// ========= fused base-2 gumbel softmax + entropy + emb GEMM =================
__global__ __launch_bounds__(128, 2) void softemb(
    const float* __restrict__ lbuf, const float* __restrict__ u,
    const __nv_bfloat16* __restrict__ we, const float* __restrict__ be,
    float* __restrict__ seq, float* __restrict__ ent,
    __nv_bfloat16* __restrict__ Ebf, int l)
{
    extern __shared__ __align__(1024) char dsm[];
    const int tid = threadIdx.x, wid = tid >> 5, lane = tid & 31;
    const int b0 = blockIdx.x << 4;
    const uint32_t smbase = (uint32_t)__cvta_generic_to_shared(dsm);
    const uint32_t sB = smbase + 16384u;
    const int cr = tid >> 2, cc = tid & 3;

    auto issueWe = [&](int kb, int s) {
        uint32_t sb = sB + ((uint32_t)s << 14);
#pragma unroll
        for (int it = 0; it < 8; ++it) {
            int rr = cr + (it << 5);
            cp16(sb + SWZ(rr, cc), we + (size_t)rr * 512 + (kb << 5) + (cc << 3));
        }
    };
    issueWe(0, 0); CP_COMMIT;
    issueWe(1, 1); CP_COMMIT;
    issueWe(2, 2); CP_COMMIT;

    // ---- softmax: warp wid handles rows wid*4..wid*4+3 ----
#pragma unroll 1
    for (int rr = 0; rr < 4; ++rr) {
        int row = (wid << 2) + rr;
        int gb = b0 + row;
        const float* lrow = lbuf + (size_t)gb * 512;
        const float* urow = u + (size_t)gb * 512;
        float v[16];
        float m = -INFINITY;
#pragma unroll
        for (int i = 0; i < 16; ++i) {
            float uu = __ldg(urow + lane + 32 * i);
            float s = __log2f(-__log2f(uu));
            v[i] = fmaf(lrow[lane + 32 * i], LOG2E, -s);
            m = fmaxf(m, v[i]);
        }
#pragma unroll
        for (int o = 16; o; o >>= 1) m = fmaxf(m, __shfl_xor_sync(0xffffffffu, m, o));
        float sum = 0.f, ews = 0.f;
#pragma unroll
        for (int i = 0; i < 16; ++i) {
            float w = v[i] - m;
            float e = exp2f(w);
            v[i] = e;
            sum += e;
            ews = fmaf(e, w, ews);
        }
#pragma unroll
        for (int o = 16; o; o >>= 1) {
            sum += __shfl_xor_sync(0xffffffffu, sum, o);
            ews += __shfl_xor_sync(0xffffffffu, ews, o);
        }
        float inv = 1.f / sum;
        float* srow = seq + ((size_t)gb * Ldim + l) * 512;
#pragma unroll
        for (int i = 0; i < 16; ++i) {
            float p = v[i] * inv;
            srow[lane + 32 * i] = p;
            uint32_t off = ((uint32_t)i << 10) + SWZ(row, (lane >> 3) & 3)
                           + ((lane & 7) << 1);
            *(__nv_bfloat16*)(dsm + off) = __float2bfloat16_rn(p);
        }
        if (lane == 0)
            ent[(size_t)gb * Ldim + l] = __log2f(sum) - ews * inv;
    }
    __syncthreads();

    // ---- emb GEMM: sample[16,512] @ We[256,512]^T; warp = 64 N-cols ----
    float acc2[8][4];
#pragma unroll
    for (int b_ = 0; b_ < 8; b_++)
#pragma unroll
        for (int c_ = 0; c_ < 4; c_++) acc2[b_][c_] = 0.f;
    const int arowe = (lane & 7) + (((lane >> 3) & 1) << 3);
    const int acb = (lane >> 4) & 1, bcb = (lane >> 3) & 1;
    const int nrowe = (wid << 6) + (lane & 7) + (((lane >> 4) & 1) << 3);
#pragma unroll 1
    for (int kb = 0; kb < 16; ++kb) {
        CP_WAIT2;
        __syncthreads();
        if (kb + 3 < 16) issueWe(kb + 3, (kb + 3) & 3);
        CP_COMMIT;
        uint32_t ab = smbase + ((uint32_t)kb << 10);
        uint32_t bb = sB + ((uint32_t)(kb & 3) << 14);
#pragma unroll
        for (int ks = 0; ks < 2; ++ks) {
            uint32_t afr[4];
            LDM_X4(afr, ab + SWZ(arowe, (ks << 1) + acb));
            uint32_t bfr[8][2];
#pragma unroll
            for (int p = 0; p < 4; ++p) {
                uint32_t t4[4];
                LDM_X4(t4, bb + SWZ(nrowe + (p << 4), (ks << 1) + bcb));
                bfr[2 * p][0] = t4[0]; bfr[2 * p][1] = t4[1];
                bfr[2 * p + 1][0] = t4[2]; bfr[2 * p + 1][1] = t4[3];
            }
#pragma unroll
            for (int nt = 0; nt < 8; ++nt)
                MMA_BF16(acc2[nt], afr, bfr[nt]);
        }
    }
#pragma unroll
    for (int nt = 0; nt < 8; ++nt) {
        int col = (wid << 6) + (nt << 3) + ((lane & 3) << 1);
        int row = b0 + (lane >> 2);
        float2 bv = *(const float2*)&be[col];
        __nv_bfloat162 p0 = {__float2bfloat16_rn(acc2[nt][0] + bv.x),
                             __float2bfloat16_rn(acc2[nt][1] + bv.y)};
        __nv_bfloat162 p1 = {__float2bfloat16_rn(acc2[nt][2] + bv.x),
                             __float2bfloat16_rn(acc2[nt][3] + bv.y)};
        *(__nv_bfloat162*)&Ebf[(size_t)row * 768 + col] = p0;
        *(__nv_bfloat162*)&Ebf[(size_t)(row + 8) * 768 + col] = p1;
    }
}

// ======================= host launcher ======================================
extern "C" void kernel_launch(void* const* d_in, const int* in_sizes, int n_in,
                              void* d_out, int out_size)
{
    const float* x       = (const float*)d_in[0];
    const float* noise   = (const float*)d_in[1];
    const float* W_agent = (const float*)d_in[2];
    const float* b_agent = (const float*)d_in[3];
    const float* W_ih    = (const float*)d_in[4];
    const float* W_hh    = (const float*)d_in[5];
    const float* b_ih    = (const float*)d_in[6];
    const float* b_hh    = (const float*)d_in[7];
    const float* W_out   = (const float*)d_in[8];
    const float* b_out   = (const float*)d_in[9];
    const float* W_emb   = (const float*)d_in[10];
    const float* b_emb   = (const float*)d_in[11];
    const float* sos     = (const float*)d_in[12];

    float* out = (float*)d_out;
    float* ent = out + (size_t)Bdim * Ldim * 512;

    float *hbuf0, *lbuf, *brz;
    __nv_bfloat16 *abf0, *grzb, *inbb, *xbf, *wrz, *wihn, *whhn, *wo, *we, *wa;
    cudaGetSymbolAddress((void**)&hbuf0, g_h);
    float* hbuf1 = hbuf0 + (size_t)Bdim * 512;
    cudaGetSymbolAddress((void**)&abf0, g_abf);
    __nv_bfloat16* abf1 = abf0 + (size_t)Bdim * 768;
    cudaGetSymbolAddress((void**)&grzb, g_grzb);
    cudaGetSymbolAddress((void**)&inbb, g_inb);
    cudaGetSymbolAddress((void**)&lbuf, g_logits);
    cudaGetSymbolAddress((void**)&xbf, g_xbf);
    cudaGetSymbolAddress((void**)&wrz, g_wrz);
    cudaGetSymbolAddress((void**)&wihn, g_wihn);
    cudaGetSymbolAddress((void**)&whhn, g_whhn);
    cudaGetSymbolAddress((void**)&wo, g_wo);
    cudaGetSymbolAddress((void**)&we, g_we);
    cudaGetSymbolAddress((void**)&wa, g_wa);
    cudaGetSymbolAddress((void**)&brz, g_brz);

    cudaFuncSetAttribute(softemb, cudaFuncAttributeMaxDynamicSharedMemorySize, 81920);

    // ---- one-time prep (single kernel) ----
    prep_all<<<19460, 256>>>(x, W_ih, W_hh, b_ih, b_hh, W_out, W_emb, W_agent, sos);

    // h0 = x @ Wa^T + ba (fp32 master + bf16 into A'[0] h-slot)
    gemm_bf<4><<<dim3(4, 32), 128>>>(xbf, 512, wa, 512, b_agent,
                                     hbuf0, 512, abf0 + 256, 768);

    for (int l = 0; l < Ldim; l++) {
        __nv_bfloat16* Ain  = (l & 1) ? abf1 : abf0;
        __nv_bfloat16* Anxt = (l & 1) ? abf0 : abf1;
        float* hin  = (l & 1) ? hbuf1 : hbuf0;
        float* hout = (l & 1) ? hbuf0 : hbuf1;

        // rz (sigmoid->bf16) + i_n (bf16) merged (512 blocks)
        gates_kernel<<<512, 128>>>(Ain, wrz, brz, wihn, b_ih + 1024, grzb, inbb);
        // h_n GEMM + fused GRU (512 blocks of 32x128, 3/SM)
        gemm_hn_gru<<<dim3(4, 128), 128>>>(Ain + 256, whhn, b_hh + 1024,
                                           grzb, inbb, hin, hout, Anxt);
        // logits = h_t @ W_out^T + b_out (256 blocks, MFR2)
        gemm_bf<2><<<dim3(4, 64), 128>>>(Anxt + 256, 768, wo, 512, b_out,
                                         lbuf, 512, (__nv_bfloat16*)0, 0);
        // softmax + entropy + emb -> out, ent, Anxt e-slot (256 blocks)
        softemb<<<256, 128, 81920>>>(
            lbuf, noise + (size_t)l * Bdim * 512, we, b_emb, out, ent, Anxt, l);
    }
    (void)in_sizes; (void)n_in; (void)out_size;
}

// round 16
// speedup vs baseline: 1.0752x; 1.0752x over previous
#include <cuda_runtime.h>
#include <cuda_bf16.h>
#include <math.h>
#include <stdint.h>

#define Bdim 4096
#define Ldim 32
#define LOG2E 1.4426950408889634f

// ---------------- scratch (device globals; no allocation allowed) ----------
__device__ float         g_h[2][(size_t)Bdim * 512];       // fp32 hidden
__device__ __nv_bfloat16 g_abf[2][(size_t)Bdim * 768];     // [e | h] bf16
__device__ __nv_bfloat16 g_grzb[(size_t)Bdim * 1024];      // sigma(r)|sigma(z) bf16
__device__ __nv_bfloat16 g_inb[(size_t)Bdim * 512];        // i_n (+b) bf16
__device__ float         g_logits[(size_t)Bdim * 512];
__device__ __nv_bfloat16 g_xbf[(size_t)Bdim * 512];
__device__ __nv_bfloat16 g_wrz[1024 * 768];
__device__ __nv_bfloat16 g_wihn[512 * 256];
__device__ __nv_bfloat16 g_whhn[512 * 512];
__device__ __nv_bfloat16 g_wo[512 * 512];
__device__ __nv_bfloat16 g_we[256 * 512];
__device__ __nv_bfloat16 g_wa[512 * 512];
__device__ float         g_brz[1024];

// fast sigmoid / tanh via MUFU ex2.approx + rcp (err ~1e-6; noise floor 1.3e-4)
__device__ __forceinline__ float sigm(float x) {
    return __fdividef(1.f, 1.f + __expf(-x));
}
__device__ __forceinline__ float tanh_fast(float x) {
    return 1.f - __fdividef(2.f, __expf(2.f * x) + 1.f);
}

#define MMA_BF16(d, a, b) \
    asm volatile("mma.sync.aligned.m16n8k16.row.col.f32.bf16.bf16.f32 " \
        "{%0,%1,%2,%3}, {%4,%5,%6,%7}, {%8,%9}, {%0,%1,%2,%3};" \
        : "+f"((d)[0]), "+f"((d)[1]), "+f"((d)[2]), "+f"((d)[3]) \
        : "r"((a)[0]), "r"((a)[1]), "r"((a)[2]), "r"((a)[3]), \
          "r"((b)[0]), "r"((b)[1]))

#define LDM_X4(d, addr) \
    asm volatile("ldmatrix.sync.aligned.m8n8.x4.shared.b16 {%0,%1,%2,%3}, [%4];" \
        : "=r"((d)[0]), "=r"((d)[1]), "=r"((d)[2]), "=r"((d)[3]) : "r"(addr))

__device__ __forceinline__ void cp16(uint32_t dst, const void* src) {
    asm volatile("cp.async.cg.shared.global [%0], [%1], 16;" :: "r"(dst), "l"(src) : "memory");
}
#define CP_COMMIT  asm volatile("cp.async.commit_group;" ::: "memory")
#define CP_WAIT2   asm volatile("cp.async.wait_group 2;" ::: "memory")

#define SWZ(r, c) ((uint32_t)((((r) << 2) + ((c) ^ (((r) >> 1) & 3))) << 4))

// ---------------- single segmented prep kernel ------------------------------
__global__ void prep_all(
    const float* __restrict__ x, const float* __restrict__ Wih,
    const float* __restrict__ Whh, const float* __restrict__ bih,
    const float* __restrict__ bhh, const float* __restrict__ Wo,
    const float* __restrict__ We, const float* __restrict__ Wa,
    const float* __restrict__ sos)
{
    size_t i = (size_t)blockIdx.x * 256 + threadIdx.x;
    if (i < 786432) {                       // wrz [1024 x 768]
        int g = (int)(i / 768), c = (int)(i % 768);
        float v = (c < 256) ? Wih[g * 256 + c] : Whh[g * 512 + (c - 256)];
        g_wrz[i] = __float2bfloat16_rn(v);
    } else if (i < 917504) {                // wihn
        size_t t = i - 786432;
        g_wihn[t] = __float2bfloat16_rn(Wih[1024 * 256 + t]);
    } else if (i < 1179648) {               // whhn
        size_t t = i - 917504;
        g_whhn[t] = __float2bfloat16_rn(Whh[1024 * 512 + t]);
    } else if (i < 1441792) {               // wo
        size_t t = i - 1179648;
        g_wo[t] = __float2bfloat16_rn(Wo[t]);
    } else if (i < 1572864) {               // we
        size_t t = i - 1441792;
        g_we[t] = __float2bfloat16_rn(We[t]);
    } else if (i < 1835008) {               // wa
        size_t t = i - 1572864;
        g_wa[t] = __float2bfloat16_rn(Wa[t]);
    } else if (i < 3932160) {               // xbf
        size_t t = i - 1835008;
        g_xbf[t] = __float2bfloat16_rn(x[t]);
    } else if (i < 4980736) {               // e0 broadcast
        size_t t = i - 3932160;
        int b = (int)(t >> 8), c = (int)(t & 255);
        g_abf[0][(size_t)b * 768 + c] = __float2bfloat16_rn(sos[c]);
    } else if (i < 4981760) {               // brz
        size_t t = i - 4980736;
        g_brz[t] = bih[t] + bhh[t];
    }
}

// =================== GEMM mainloop (device function) ========================
template<int MFR>
__device__ __forceinline__ void gemm_mainloop(
    char* smem, int tid,
    const __nv_bfloat16* __restrict__ A, int lda,
    const __nv_bfloat16* __restrict__ W, int ldw, int KB,
    int m0, int n0, float acc[MFR][8][4])
{
    constexpr int AS = MFR * 2048;
    constexpr int SS = AS + 8192;
    const int wid = tid >> 5, lane = tid & 31;
    const int wm = wid & 1, wn = wid >> 1;
    const uint32_t smbase = (uint32_t)__cvta_generic_to_shared(smem);

#pragma unroll
    for (int a_ = 0; a_ < MFR; a_++)
#pragma unroll
        for (int b_ = 0; b_ < 8; b_++)
#pragma unroll
            for (int c_ = 0; c_ < 4; c_++) acc[a_][b_][c_] = 0.f;

    const int cr = tid >> 2, cc = tid & 3;
    auto issue = [&](int kb, int s) {
        uint32_t sb = smbase + (uint32_t)s * SS;
#pragma unroll
        for (int it = 0; it < MFR; ++it) {
            int rr = cr + (it << 5);
            cp16(sb + SWZ(rr, cc), A + (size_t)(m0 + rr) * lda + (kb << 5) + (cc << 3));
        }
#pragma unroll
        for (int it = 0; it < 4; ++it) {
            int rr = cr + (it << 5);
            cp16(sb + AS + SWZ(rr, cc), W + (size_t)(n0 + rr) * ldw + (kb << 5) + (cc << 3));
        }
    };
    const int arow0 = wm * (MFR << 4) + (lane & 7) + (((lane >> 3) & 1) << 3);
    const int acb   = (lane >> 4) & 1;
    const int nrow0 = (wn << 6) + (lane & 7) + (((lane >> 4) & 1) << 3);
    const int bcb   = (lane >> 3) & 1;

    issue(0, 0); CP_COMMIT;
    issue(1, 1); CP_COMMIT;
    issue(2, 2); CP_COMMIT;
#pragma unroll 1
    for (int kb = 0; kb < KB; ++kb) {
        CP_WAIT2;
        __syncthreads();
        if (kb + 3 < KB) issue(kb + 3, (kb + 3) & 3);
        CP_COMMIT;
        uint32_t ab = smbase + (uint32_t)(kb & 3) * SS, bb = ab + AS;
#pragma unroll
        for (int ks = 0; ks < 2; ++ks) {
            uint32_t afr[MFR][4];
#pragma unroll
            for (int mt = 0; mt < MFR; ++mt)
                LDM_X4(afr[mt], ab + SWZ(arow0 + (mt << 4), (ks << 1) + acb));
            uint32_t bfr[8][2];
#pragma unroll
            for (int p = 0; p < 4; ++p) {
                uint32_t t4[4];
                LDM_X4(t4, bb + SWZ(nrow0 + (p << 4), (ks << 1) + bcb));
                bfr[2 * p][0] = t4[0]; bfr[2 * p][1] = t4[1];
                bfr[2 * p + 1][0] = t4[2]; bfr[2 * p + 1][1] = t4[3];
            }
#pragma unroll
            for (int mt = 0; mt < MFR; ++mt)
#pragma unroll
                for (int nt = 0; nt < 8; ++nt)
                    MMA_BF16(acc[mt][nt], afr[mt], bfr[nt]);
        }
    }
}

// ---- generic fp32(+bf16) epilogue ----
template<int MFR>
__device__ __forceinline__ void epi_store(
    float acc[MFR][8][4], int tid,
    const float* __restrict__ bias,
    float* __restrict__ C, int ldc,
    __nv_bfloat16* __restrict__ Cbf, int ldcb,
    int m0, int n0)
{
    const int wid = tid >> 5, lane = tid & 31;
    const int wm = wid & 1, wn = wid >> 1;
#pragma unroll
    for (int mt = 0; mt < MFR; ++mt) {
#pragma unroll
        for (int nt = 0; nt < 8; ++nt) {
            int row = m0 + wm * (MFR << 4) + (mt << 4) + (lane >> 2);
            int col = n0 + (wn << 6) + (nt << 3) + ((lane & 3) << 1);
            float2 bv = *(const float2*)&bias[col];
            float2 o0 = {acc[mt][nt][0] + bv.x, acc[mt][nt][1] + bv.y};
            float2 o1 = {acc[mt][nt][2] + bv.x, acc[mt][nt][3] + bv.y};
            if (C) {
                *(float2*)&C[(size_t)row * ldc + col] = o0;
                *(float2*)&C[(size_t)(row + 8) * ldc + col] = o1;
            }
            if (Cbf) {
                __nv_bfloat162 p0 = {__float2bfloat16_rn(o0.x), __float2bfloat16_rn(o0.y)};
                __nv_bfloat162 p1 = {__float2bfloat16_rn(o1.x), __float2bfloat16_rn(o1.y)};
                *(__nv_bfloat162*)&Cbf[(size_t)row * ldcb + col] = p0;
                *(__nv_bfloat162*)&Cbf[(size_t)(row + 8) * ldcb + col] = p1;
            }
        }
    }
}

// ======================= generic bf16 GEMM ==================================
template<int MFR>
__global__ __launch_bounds__(128, 2) void gemm_bf(
    const __nv_bfloat16* __restrict__ A, int lda,
    const __nv_bfloat16* __restrict__ W, int K,
    const float* __restrict__ bias,
    float* __restrict__ C, int ldc,
    __nv_bfloat16* __restrict__ Cbf, int ldcb)
{
    __shared__ __align__(1024) char smem[(MFR * 2048 + 8192) * 4];
    const int tid = threadIdx.x;
    const int m0 = blockIdx.y * (MFR << 5), n0 = blockIdx.x << 7;
    float acc[MFR][8][4];
    gemm_mainloop<MFR>(smem, tid, A, lda, W, K, K >> 5, m0, n0, acc);
    epi_store<MFR>(acc, tid, bias, C, ldc, Cbf, ldcb, m0, n0);
}

// ====== merged gates kernel: rz (fast sigmoid->bf16) + i_n (bf16) ==========
__global__ __launch_bounds__(128, 2) void gates_kernel(
    const __nv_bfloat16* __restrict__ Ain,   // [B,768] bf16
    const __nv_bfloat16* __restrict__ wrz,   // [1024,768]
    const float* __restrict__ brz,
    const __nv_bfloat16* __restrict__ wihn,  // [512,256]
    const float* __restrict__ bihn,
    __nv_bfloat16* __restrict__ grzb,        // [B,1024] sigma bf16
    __nv_bfloat16* __restrict__ inbb)        // [B,512] bf16
{
    __shared__ __align__(1024) char smem[(4 * 2048 + 8192) * 4];
    const int tid = threadIdx.x, wid = tid >> 5, lane = tid & 31;
    const int wm = wid & 1, wn = wid >> 1;
    const int j = blockIdx.x;
    if (j < 256) {
        int m0 = (j >> 3) << 7, n0 = (j & 7) << 7;
        float acc[4][8][4];
        gemm_mainloop<4>(smem, tid, Ain, 768, wrz, 768, 24, m0, n0, acc);
#pragma unroll
        for (int mt = 0; mt < 4; ++mt) {
#pragma unroll
            for (int nt = 0; nt < 8; ++nt) {
                int row = m0 + (wm << 6) + (mt << 4) + (lane >> 2);
                int col = n0 + (wn << 6) + (nt << 3) + ((lane & 3) << 1);
                float2 bv = *(const float2*)&brz[col];
                __nv_bfloat162 p0 = {__float2bfloat16_rn(sigm(acc[mt][nt][0] + bv.x)),
                                     __float2bfloat16_rn(sigm(acc[mt][nt][1] + bv.y))};
                __nv_bfloat162 p1 = {__float2bfloat16_rn(sigm(acc[mt][nt][2] + bv.x)),
                                     __float2bfloat16_rn(sigm(acc[mt][nt][3] + bv.y))};
                *(__nv_bfloat162*)&grzb[(size_t)row * 1024 + col] = p0;
                *(__nv_bfloat162*)&grzb[(size_t)(row + 8) * 1024 + col] = p1;
            }
        }
    } else {
        int t = j - 256;
        int m0 = (t >> 2) << 6, n0 = (t & 3) << 7;
        float acc[2][8][4];
        gemm_mainloop<2>(smem, tid, Ain, 768, wihn, 256, 8, m0, n0, acc);
        epi_store<2>(acc, tid, bihn, (float*)0, 0, inbb, 512, m0, n0);
    }
}

// ================= h_n GEMM with fused GRU update ===========================
__global__ __launch_bounds__(128, 3) void gemm_hn_gru(
    const __nv_bfloat16* __restrict__ A,    // h bf16 (ld 768)
    const __nv_bfloat16* __restrict__ W,    // Whh_n [512,512]
    const float* __restrict__ bias,         // b_hh_n
    const __nv_bfloat16* __restrict__ grzb, // [B,1024] sigma(r)|sigma(z) bf16
    const __nv_bfloat16* __restrict__ inbb, // [B,512] i_n (+b) bf16
    const float* __restrict__ hin,          // [B,512] fp32
    float* __restrict__ hout,
    __nv_bfloat16* __restrict__ habf)       // Anxt base; h at +256, ld 768
{
    __shared__ __align__(1024) char smem[(1 * 2048 + 8192) * 4];   // 40K
    const int tid = threadIdx.x, wid = tid >> 5, lane = tid & 31;
    const int wm = wid & 1, wn = wid >> 1;
    const int m0 = blockIdx.y << 5, n0 = blockIdx.x << 7;

    float acc[1][8][4];
    gemm_mainloop<1>(smem, tid, A, 768, W, 512, 16, m0, n0, acc);

    __syncthreads();
    float* st = (float*)smem;               // [32][132]
#pragma unroll
    for (int nt = 0; nt < 8; ++nt) {
        int rl = (wm << 4) + (lane >> 2);
        int col = (wn << 6) + (nt << 3) + ((lane & 3) << 1);
        float2 bv = *(const float2*)&bias[n0 + col];
        float2 s0 = {acc[0][nt][0] + bv.x, acc[0][nt][1] + bv.y};
        float2 s1 = {acc[0][nt][2] + bv.x, acc[0][nt][3] + bv.y};
        *(float2*)&st[rl * 132 + col] = s0;
        *(float2*)&st[(rl + 8) * 132 + col] = s1;
    }
    __syncthreads();

#pragma unroll
    for (int t = 0; t < 8; ++t) {
        int idx = tid + (t << 7);
        int r = idx >> 5, q = idx & 31;
        int rg = m0 + r, jg = n0 + (q << 2);
        float4 hn = *(float4*)&st[r * 132 + (q << 2)];
        __nv_bfloat162 rv0 = *(const __nv_bfloat162*)&grzb[(size_t)rg * 1024 + jg];
        __nv_bfloat162 rv1 = *(const __nv_bfloat162*)&grzb[(size_t)rg * 1024 + jg + 2];
        __nv_bfloat162 zv0 = *(const __nv_bfloat162*)&grzb[(size_t)rg * 1024 + 512 + jg];
        __nv_bfloat162 zv1 = *(const __nv_bfloat162*)&grzb[(size_t)rg * 1024 + 512 + jg + 2];
        __nv_bfloat162 iv0 = *(const __nv_bfloat162*)&inbb[(size_t)rg * 512 + jg];
        __nv_bfloat162 iv1 = *(const __nv_bfloat162*)&inbb[(size_t)rg * 512 + jg + 2];
        float4 hh = *(const float4*)&hin[(size_t)rg * 512 + jg];
        float4 o;
        { float rs = __bfloat162float(rv0.x), zs = __bfloat162float(zv0.x);
          o.x = (1.f - zs) * tanh_fast(__bfloat162float(iv0.x) + rs * hn.x) + zs * hh.x; }
        { float rs = __bfloat162float(rv0.y), zs = __bfloat162float(zv0.y);
          o.y = (1.f - zs) * tanh_fast(__bfloat162float(iv0.y) + rs * hn.y) + zs * hh.y; }
        { float rs = __bfloat162float(rv1.x), zs = __bfloat162float(zv1.x);
          o.z = (1.f - zs) * tanh_fast(__bfloat162float(iv1.x) + rs * hn.z) + zs * hh.z; }
        { float rs = __bfloat162float(rv1.y), zs = __bfloat162float(zv1.y);
          o.w = (1.f - zs) * tanh_fast(__bfloat162float(iv1.y) + rs * hn.w) + zs * hh.w; }
        *(float4*)&hout[(size_t)rg * 512 + jg] = o;
        __nv_bfloat162 p0 = {__float2bfloat16_rn(o.x), __float2bfloat16_rn(o.y)};
        __nv_bfloat162 p1 = {__float2bfloat16_rn(o.z), __float2bfloat16_rn(o.w)};
        __nv_bfloat162* dst = (__nv_bfloat162*)(habf + (size_t)rg * 768 + 256 + jg);
        dst[0] = p0; dst[1] = p1;
    }
}

// ========= fused base-2 gumbel softmax + entropy + emb GEMM =================
__global__ __launch_bounds__(128, 2) void softemb(
    const float* __restrict__ lbuf, const float* __restrict__ u,
    const __nv_bfloat16* __restrict__ we, const float* __restrict__ be,
    float* __restrict__ seq, float* __restrict__ ent,
    __nv_bfloat16* __restrict__ Ebf, int l)
{
    extern __shared__ __align__(1024) char dsm[];
    const int tid = threadIdx.x, wid = tid >> 5, lane = tid & 31;
    const int b0 = blockIdx.x << 4;
    const uint32_t smbase = (uint32_t)__cvta_generic_to_shared(dsm);
    const uint32_t sB = smbase + 16384u;
    const int cr = tid >> 2, cc = tid & 3;

    auto issueWe = [&](int kb, int s) {
        uint32_t sb = sB + ((uint32_t)s << 14);
#pragma unroll
        for (int it = 0; it < 8; ++it) {
            int rr = cr + (it << 5);
            cp16(sb + SWZ(rr, cc), we + (size_t)rr * 512 + (kb << 5) + (cc << 3));
        }
    };
    issueWe(0, 0); CP_COMMIT;
    issueWe(1, 1); CP_COMMIT;
    issueWe(2, 2); CP_COMMIT;

    // ---- softmax: warp wid handles rows wid*4..wid*4+3 ----
#pragma unroll 1
    for (int rr = 0; rr < 4; ++rr) {
        int row = (wid << 2) + rr;
        int gb = b0 + row;
        const float* lrow = lbuf + (size_t)gb * 512;
        const float* urow = u + (size_t)gb * 512;
        float v[16];
        float m = -INFINITY;
#pragma unroll
        for (int i = 0; i < 16; ++i) {
            float uu = __ldg(urow + lane + 32 * i);
            float s = __log2f(-__log2f(uu));
            v[i] = fmaf(lrow[lane + 32 * i], LOG2E, -s);
            m = fmaxf(m, v[i]);
        }
#pragma unroll
        for (int o = 16; o; o >>= 1) m = fmaxf(m, __shfl_xor_sync(0xffffffffu, m, o));
        float sum = 0.f, ews = 0.f;
#pragma unroll
        for (int i = 0; i < 16; ++i) {
            float w = v[i] - m;
            float e = exp2f(w);
            v[i] = e;
            sum += e;
            ews = fmaf(e, w, ews);
        }
#pragma unroll
        for (int o = 16; o; o >>= 1) {
            sum += __shfl_xor_sync(0xffffffffu, sum, o);
            ews += __shfl_xor_sync(0xffffffffu, ews, o);
        }
        float inv = 1.f / sum;
        float* srow = seq + ((size_t)gb * Ldim + l) * 512;
#pragma unroll
        for (int i = 0; i < 16; ++i) {
            float p = v[i] * inv;
            srow[lane + 32 * i] = p;
            uint32_t off = ((uint32_t)i << 10) + SWZ(row, (lane >> 3) & 3)
                           + ((lane & 7) << 1);
            *(__nv_bfloat16*)(dsm + off) = __float2bfloat16_rn(p);
        }
        if (lane == 0)
            ent[(size_t)gb * Ldim + l] = __log2f(sum) - ews * inv;
    }
    __syncthreads();

    // ---- emb GEMM: sample[16,512] @ We[256,512]^T; warp = 64 N-cols ----
    float acc2[8][4];
#pragma unroll
    for (int b_ = 0; b_ < 8; b_++)
#pragma unroll
        for (int c_ = 0; c_ < 4; c_++) acc2[b_][c_] = 0.f;
    const int arowe = (lane & 7) + (((lane >> 3) & 1) << 3);
    const int acb = (lane >> 4) & 1, bcb = (lane >> 3) & 1;
    const int nrowe = (wid << 6) + (lane & 7) + (((lane >> 4) & 1) << 3);
#pragma unroll 1
    for (int kb = 0; kb < 16; ++kb) {
        CP_WAIT2;
        __syncthreads();
        if (kb + 3 < 16) issueWe(kb + 3, (kb + 3) & 3);
        CP_COMMIT;
        uint32_t ab = smbase + ((uint32_t)kb << 10);
        uint32_t bb = sB + ((uint32_t)(kb & 3) << 14);
#pragma unroll
        for (int ks = 0; ks < 2; ++ks) {
            uint32_t afr[4];
            LDM_X4(afr, ab + SWZ(arowe, (ks << 1) + acb));
            uint32_t bfr[8][2];
#pragma unroll
            for (int p = 0; p < 4; ++p) {
                uint32_t t4[4];
                LDM_X4(t4, bb + SWZ(nrowe + (p << 4), (ks << 1) + bcb));
                bfr[2 * p][0] = t4[0]; bfr[2 * p][1] = t4[1];
                bfr[2 * p + 1][0] = t4[2]; bfr[2 * p + 1][1] = t4[3];
            }
#pragma unroll
            for (int nt = 0; nt < 8; ++nt)
                MMA_BF16(acc2[nt], afr, bfr[nt]);
        }
    }
#pragma unroll
    for (int nt = 0; nt < 8; ++nt) {
        int col = (wid << 6) + (nt << 3) + ((lane & 3) << 1);
        int row = b0 + (lane >> 2);
        float2 bv = *(const float2*)&be[col];
        __nv_bfloat162 p0 = {__float2bfloat16_rn(acc2[nt][0] + bv.x),
                             __float2bfloat16_rn(acc2[nt][1] + bv.y)};
        __nv_bfloat162 p1 = {__float2bfloat16_rn(acc2[nt][2] + bv.x),
                             __float2bfloat16_rn(acc2[nt][3] + bv.y)};
        *(__nv_bfloat162*)&Ebf[(size_t)row * 768 + col] = p0;
        *(__nv_bfloat162*)&Ebf[(size_t)(row + 8) * 768 + col] = p1;
    }
}

// ======================= host launcher ======================================
extern "C" void kernel_launch(void* const* d_in, const int* in_sizes, int n_in,
                              void* d_out, int out_size)
{
    const float* x       = (const float*)d_in[0];
    const float* noise   = (const float*)d_in[1];
    const float* W_agent = (const float*)d_in[2];
    const float* b_agent = (const float*)d_in[3];
    const float* W_ih    = (const float*)d_in[4];
    const float* W_hh    = (const float*)d_in[5];
    const float* b_ih    = (const float*)d_in[6];
    const float* b_hh    = (const float*)d_in[7];
    const float* W_out   = (const float*)d_in[8];
    const float* b_out   = (const float*)d_in[9];
    const float* W_emb   = (const float*)d_in[10];
    const float* b_emb   = (const float*)d_in[11];
    const float* sos     = (const float*)d_in[12];

    float* out = (float*)d_out;
    float* ent = out + (size_t)Bdim * Ldim * 512;

    float *hbuf0, *lbuf, *brz;
    __nv_bfloat16 *abf0, *grzb, *inbb, *xbf, *wrz, *wihn, *whhn, *wo, *we, *wa;
    cudaGetSymbolAddress((void**)&hbuf0, g_h);
    float* hbuf1 = hbuf0 + (size_t)Bdim * 512;
    cudaGetSymbolAddress((void**)&abf0, g_abf);
    __nv_bfloat16* abf1 = abf0 + (size_t)Bdim * 768;
    cudaGetSymbolAddress((void**)&grzb, g_grzb);
    cudaGetSymbolAddress((void**)&inbb, g_inb);
    cudaGetSymbolAddress((void**)&lbuf, g_logits);
    cudaGetSymbolAddress((void**)&xbf, g_xbf);
    cudaGetSymbolAddress((void**)&wrz, g_wrz);
    cudaGetSymbolAddress((void**)&wihn, g_wihn);
    cudaGetSymbolAddress((void**)&whhn, g_whhn);
    cudaGetSymbolAddress((void**)&wo, g_wo);
    cudaGetSymbolAddress((void**)&we, g_we);
    cudaGetSymbolAddress((void**)&wa, g_wa);
    cudaGetSymbolAddress((void**)&brz, g_brz);

    cudaFuncSetAttribute(softemb, cudaFuncAttributeMaxDynamicSharedMemorySize, 81920);

    // ---- one-time prep (single kernel) ----
    prep_all<<<19460, 256>>>(x, W_ih, W_hh, b_ih, b_hh, W_out, W_emb, W_agent, sos);

    // h0 = x @ Wa^T + ba (fp32 master + bf16 into A'[0] h-slot)
    gemm_bf<4><<<dim3(4, 32), 128>>>(xbf, 512, wa, 512, b_agent,
                                     hbuf0, 512, abf0 + 256, 768);

    for (int l = 0; l < Ldim; l++) {
        __nv_bfloat16* Ain  = (l & 1) ? abf1 : abf0;
        __nv_bfloat16* Anxt = (l & 1) ? abf0 : abf1;
        float* hin  = (l & 1) ? hbuf1 : hbuf0;
        float* hout = (l & 1) ? hbuf0 : hbuf1;

        // rz (fast sigmoid->bf16) + i_n (bf16) merged (512 blocks)
        gates_kernel<<<512, 128>>>(Ain, wrz, brz, wihn, b_ih + 1024, grzb, inbb);
        // h_n GEMM + fused GRU (512 blocks of 32x128, 3/SM)
        gemm_hn_gru<<<dim3(4, 128), 128>>>(Ain + 256, whhn, b_hh + 1024,
                                           grzb, inbb, hin, hout, Anxt);
        // logits = h_t @ W_out^T + b_out (256 blocks, MFR2)
        gemm_bf<2><<<dim3(4, 64), 128>>>(Anxt + 256, 768, wo, 512, b_out,
                                         lbuf, 512, (__nv_bfloat16*)0, 0);
        // softmax + entropy + emb -> out, ent, Anxt e-slot (256 blocks)
        softemb<<<256, 128, 81920>>>(
            lbuf, noise + (size_t)l * Bdim * 512, we, b_emb, out, ent, Anxt, l);
    }
    (void)in_sizes; (void)n_in; (void)out_size;
}